// round 8
// baseline (speedup 1.0000x reference)
#include <cuda_runtime.h>
#include <cuda_bf16.h>
#include <cstdint>

#define MSZ 16384
#define NSZ 2048
#define KSZ 2048
#define KK (2 * KSZ)                      // virtual K (digit pairs interleaved)
#define BM 128
#define BN 128
#define BKK 128                           // virtual-k bytes per tile
#define KTILES (KK / BKK)                 // 32
#define THREADS 256
#define PLANE_BYTES (128 * 128)           // 16KB per plane per stage
#define STAGE_BYTES (3 * PLANE_BYTES)     // A01 + A23 + B' = 48KB
#define NSTAGE 3
#define SMEM_BYTES (NSTAGE * STAGE_BYTES) // 144KB

#define DRANGE 42000000                   // clamp for base-96 4-digit balanced rep
#define QCONST (8.0f / 42000000.0f)       // q = |inS*wS| * QCONST  (range = ±8 sigma)

// -------- scratch (device globals: the allowed scratch mechanism) --------
__device__ __align__(16) signed char g_A01[(size_t)MSZ * KK];   // digits d0,d1 interleaved
__device__ __align__(16) signed char g_A23[(size_t)MSZ * KK];   // digits d2,d3 interleaved
__device__ __align__(16) signed char g_Bp[(size_t)NSZ * KK];    // w, 96w interleaved
__device__ double g_abs_sum;
__device__ float  g_inv_scale;

// ---------------- PTX helpers (non-'a' features only: valid for compute_103) ----------------
__device__ __forceinline__ uint32_t s2u(const void* p) {
    return (uint32_t)__cvta_generic_to_shared(p);
}
__device__ __forceinline__ uint32_t swz(uint32_t off) { return off ^ ((off >> 3) & 0x70); }

__device__ __forceinline__ void cp16(uint32_t dst, const void* src) {
    asm volatile("cp.async.cg.shared.global [%0], [%1], 16;" :: "r"(dst), "l"(src));
}
__device__ __forceinline__ void cp_commit() { asm volatile("cp.async.commit_group;" ::: "memory"); }
__device__ __forceinline__ void cp_wait2()  { asm volatile("cp.async.wait_group 2;" ::: "memory"); }

__device__ __forceinline__ void ldsm_x4(uint32_t& r0, uint32_t& r1, uint32_t& r2, uint32_t& r3,
                                        uint32_t addr) {
    asm volatile("ldmatrix.sync.aligned.m8n8.x4.shared.b16 {%0,%1,%2,%3}, [%4];"
                 : "=r"(r0), "=r"(r1), "=r"(r2), "=r"(r3) : "r"(addr));
}

// s8 m16n8k32: fragment byte layout identical to bf16 m16n8k16 (4B/reg at 4*tig, k-half +16B)
__device__ __forceinline__ void mma_s8(int* d, const uint32_t* a, const uint32_t* b) {
    asm volatile(
        "mma.sync.aligned.m16n8k32.row.col.s32.s8.s8.s32 "
        "{%0,%1,%2,%3}, {%4,%5,%6,%7}, {%8,%9}, {%0,%1,%2,%3};"
        : "+r"(d[0]), "+r"(d[1]), "+r"(d[2]), "+r"(d[3])
        : "r"(a[0]), "r"(a[1]), "r"(a[2]), "r"(a[3]), "r"(b[0]), "r"(b[1]));
}

// balanced base-96 digit: returns r in [-48,47], updates d := (d-r)/96 exactly
__device__ __forceinline__ int bdig(int& d) {
    int r = d % 96;
    if (r > 47) r -= 96;
    else if (r < -48) r += 96;
    d = (d - r) / 96;
    return r;
}

// ---------------- pre-pass: base-96 digit split of t = x*inS*wS ----------------
__global__ void split_kernel(const float4* __restrict__ x,
                             const float* __restrict__ inS,
                             const float* __restrict__ wS, int n4) {
    int i = blockIdx.x * blockDim.x + threadIdx.x;
    if (i >= n4) return;
    const float s = inS[0] * wS[0];
    const float q = fabsf(s) * QCONST;
    const float f = s * (1.0f / q);          // t*inv_q == x*f
    float4 v = x[i];
    float t[4] = {v.x, v.y, v.z, v.w};
    unsigned char b01[8], b23[8];
    #pragma unroll
    for (int j = 0; j < 4; j++) {
        int d = __float2int_rn(t[j] * f);
        d = max(min(d, DRANGE), -DRANGE);
        int d0 = bdig(d), d1 = bdig(d), d2 = bdig(d), d3 = bdig(d);
        b01[2 * j] = (unsigned char)(signed char)d0;
        b01[2 * j + 1] = (unsigned char)(signed char)d1;
        b23[2 * j] = (unsigned char)(signed char)d2;
        b23[2 * j + 1] = (unsigned char)(signed char)d3;
    }
    // flat element base e = 4*i; interleaved offset = 2*e = 8*i (8B aligned)
    *(unsigned long long*)&g_A01[(size_t)i * 8] = *(unsigned long long*)b01;
    *(unsigned long long*)&g_A23[(size_t)i * 8] = *(unsigned long long*)b23;
}

__global__ void wconv_kernel(const float4* __restrict__ w, int n4) {
    int i = blockIdx.x * blockDim.x + threadIdx.x;
    if (i >= n4) return;
    float4 v = w[i];
    float t[4] = {v.x, v.y, v.z, v.w};
    unsigned char b[8];
    #pragma unroll
    for (int j = 0; j < 4; j++) {
        int wi = (int)t[j];                          // exactly -1, 0, or 1
        b[2 * j] = (unsigned char)(signed char)wi;
        b[2 * j + 1] = (unsigned char)(signed char)(96 * wi);
    }
    *(unsigned long long*)&g_Bp[(size_t)i * 8] = *(unsigned long long*)b;
}

__global__ void reset_kernel() { g_abs_sum = 0.0; }

// ---------------- IMMA GEMM (exact int32 accumulation) ----------------
__global__ __launch_bounds__(THREADS, 1)
void gemm_kernel(float* __restrict__ C,
                 const float* __restrict__ inS, const float* __restrict__ wS) {
    extern __shared__ char smem[];
    const uint32_t sb = s2u(smem);

    const int tid = threadIdx.x, wid = tid >> 5, lane = tid & 31;
    const int wm = wid & 1;          // 2 warps in m -> 64 rows each
    const int wn = wid >> 1;         // 4 warps in n -> 32 cols each
    const int m0 = blockIdx.y * BM;
    const int n0 = blockIdx.x * BN;

    int acc01[4][4][4], acc23[4][4][4];
    #pragma unroll
    for (int i = 0; i < 4; i++)
        #pragma unroll
        for (int j = 0; j < 4; j++)
            #pragma unroll
            for (int r = 0; r < 4; r++) { acc01[i][j][r] = 0; acc23[i][j][r] = 0; }

    // --- cp.async stage loader: 3 planes x 128 rows x 128B, SW128 swizzled ---
    auto load_stage = [&](int kt) {
        const uint32_t stb = sb + (uint32_t)(kt % NSTAGE) * STAGE_BYTES;
        const int kb = kt * BKK;
        #pragma unroll
        for (int p = 0; p < 3; p++) {
            const signed char* base =
                (p == 0 ? g_A01 : p == 1 ? g_A23 : g_Bp) +
                (size_t)(p == 2 ? n0 : m0) * KK + kb;
            #pragma unroll
            for (int j = 0; j < 4; j++) {
                int e = tid + THREADS * j;          // 0..1023
                int row = e >> 3, c = e & 7;
                cp16(stb + p * PLANE_BYTES + swz(row * 128 + c * 16),
                     base + (size_t)row * KK + c * 16);
            }
        }
    };

    // --- per-lane ldmatrix components (byte-identical to proven bf16 mapping) ---
    const int a_row  = wm * 64 + (lane & 15);                       // + mt*16
    const int a_koff = (lane >> 4) * 16;                            // + ks*32
    const int b_row  = wn * 32 + ((lane >> 4) << 3) + (lane & 7);   // + pair*16
    const int b_koff = ((lane >> 3) & 1) * 16;                      // + ks*32

    load_stage(0); cp_commit();
    load_stage(1); cp_commit();

    for (int kt = 0; kt < KTILES; kt++) {
        if (kt + 2 < KTILES) load_stage(kt + 2);
        cp_commit();            // uniform group count (empty group in tail)
        cp_wait2();             // stage kt resident (this thread's groups)
        __syncthreads();        // publish all threads' loads

        const uint32_t stb = sb + (uint32_t)(kt % NSTAGE) * STAGE_BYTES;
        #pragma unroll
        for (int ks = 0; ks < 4; ks++) {
            // B' fragments for all 4 n-tiles (shared by both digit pairs)
            uint32_t bfr[2][4];
            #pragma unroll
            for (int pair = 0; pair < 2; pair++) {
                uint32_t off = (uint32_t)(b_row + pair * 16) * 128 + ks * 32 + b_koff;
                ldsm_x4(bfr[pair][0], bfr[pair][1], bfr[pair][2], bfr[pair][3],
                        stb + 2 * PLANE_BYTES + swz(off));
            }
            #pragma unroll
            for (int mt = 0; mt < 4; mt++) {
                uint32_t off = (uint32_t)(a_row + mt * 16) * 128 + ks * 32 + a_koff;
                uint32_t a0[4], a1[4];
                ldsm_x4(a0[0], a0[1], a0[2], a0[3], stb + swz(off));
                ldsm_x4(a1[0], a1[1], a1[2], a1[3], stb + PLANE_BYTES + swz(off));
                #pragma unroll
                for (int nt = 0; nt < 4; nt++) {
                    mma_s8(acc01[mt][nt], a0, &bfr[nt >> 1][(nt & 1) * 2]);
                    mma_s8(acc23[mt][nt], a1, &bfr[nt >> 1][(nt & 1) * 2]);
                }
            }
        }
        __syncthreads();        // protect buffer before reload
    }

    // ---------------- epilogue: out = q*(acc01 + 9216*acc23), store + abs-sum ----------------
    const float s = inS[0] * wS[0];
    const float q = fabsf(s) * QCONST;          // identical formula to split_kernel
    float asum = 0.f;
    {
        const int rbase = m0 + wm * 64 + (lane >> 2);
        const int cbase = n0 + wn * 32 + (lane & 3) * 2;
        #pragma unroll
        for (int mt = 0; mt < 4; mt++) {
            #pragma unroll
            for (int nt = 0; nt < 4; nt++) {
                float v[4];
                #pragma unroll
                for (int r = 0; r < 4; r++) {
                    // |acc| < 2^24 -> int->float exact; one fma + one mul rounding
                    float t0 = fmaf(9216.f, (float)acc23[mt][nt][r], (float)acc01[mt][nt][r]);
                    v[r] = q * t0;
                    asum += fabsf(v[r]);
                }
                float* p0 = C + (size_t)(rbase + mt * 16) * NSZ + cbase + nt * 8;
                float* p1 = p0 + 8 * NSZ;
                *(float2*)p0 = make_float2(v[0], v[1]);
                *(float2*)p1 = make_float2(v[2], v[3]);
            }
        }
    }

    __shared__ float red[THREADS / 32];
    #pragma unroll
    for (int off = 16; off > 0; off >>= 1)
        asum += __shfl_down_sync(0xffffffffu, asum, off);
    if (lane == 0) red[wid] = asum;
    __syncthreads();
    if (wid == 0) {
        float v = (lane < THREADS / 32) ? red[lane] : 0.f;
        #pragma unroll
        for (int off = 4; off > 0; off >>= 1)
            v += __shfl_down_sync(0xffffffffu, v, off);
        if (lane == 0) atomicAdd(&g_abs_sum, (double)v);
    }
}

// ---------------- finalize + quantize ----------------
__global__ void finalize_kernel(float* __restrict__ scale_slot, size_t mn) {
    double mean = g_abs_sum / (double)mn;
    float scale = (float)mean;
    if (scale < 1e-5f) scale = 1e-5f;
    *scale_slot = scale;
    g_inv_scale = (float)(1.0 / (double)scale);
}

__global__ void quantize_kernel(float4* __restrict__ C, int n4) {
    int i = blockIdx.x * blockDim.x + threadIdx.x;
    if (i >= n4) return;
    const float inv = g_inv_scale;
    float4 v = C[i];
    v.x = fminf(fmaxf(rintf(v.x * inv), -1.f), 1.f);
    v.y = fminf(fmaxf(rintf(v.y * inv), -1.f), 1.f);
    v.z = fminf(fmaxf(rintf(v.z * inv), -1.f), 1.f);
    v.w = fminf(fmaxf(rintf(v.w * inv), -1.f), 1.f);
    C[i] = v;
}

extern "C" void kernel_launch(void* const* d_in, const int* in_sizes, int n_in,
                              void* d_out, int out_size)
{
    const float* x   = (const float*)d_in[0];
    const float* inS = (const float*)d_in[1];
    const float* qw  = (const float*)d_in[2];
    const float* wS  = (const float*)d_in[3];
    float* out = (float*)d_out;
    const size_t mn = (size_t)MSZ * NSZ;

    cudaFuncSetAttribute(gemm_kernel, cudaFuncAttributeMaxDynamicSharedMemorySize, SMEM_BYTES);

    const int a4 = MSZ * KSZ / 4;
    split_kernel<<<(a4 + 255) / 256, 256>>>((const float4*)x, inS, wS, a4);
    const int w4 = NSZ * KSZ / 4;
    wconv_kernel<<<(w4 + 255) / 256, 256>>>((const float4*)qw, w4);
    reset_kernel<<<1, 1>>>();

    dim3 grid(NSZ / BN, MSZ / BM);   // (16, 128)
    gemm_kernel<<<grid, THREADS, SMEM_BYTES>>>(out, inS, wS);

    finalize_kernel<<<1, 1>>>(out + mn, mn);

    const int n4 = (int)(mn / 4);
    quantize_kernel<<<(n4 + 255) / 256, 256>>>((float4*)out, n4);
}

// round 9
// speedup vs baseline: 1.0002x; 1.0002x over previous
#include <cuda_runtime.h>
#include <cuda_bf16.h>
#include <cstdint>

#define MSZ 16384
#define NSZ 2048
#define KSZ 2048
#define KK (2 * KSZ)                      // virtual K (digit pairs interleaved)
#define BM 128
#define BN 128
#define BKK 128                           // virtual-k bytes per tile
#define KTILES (KK / BKK)                 // 32
#define THREADS 256
#define PLANE_BYTES (128 * 128)           // 16KB per plane per stage
#define STAGE_BYTES (3 * PLANE_BYTES)     // A01 + A23 + B' = 48KB
#define NSTAGE 3
#define SMEM_BYTES (NSTAGE * STAGE_BYTES) // 144KB

#define DRANGE 42000000                   // clamp for base-96 4-digit balanced rep
#define QCONST (8.0f / 42000000.0f)       // q = |inS*wS| * QCONST  (range = ±8 sigma)

// -------- scratch (device globals: the allowed scratch mechanism) --------
__device__ __align__(16) signed char g_A01[(size_t)MSZ * KK];   // digits d0,d1 interleaved
__device__ __align__(16) signed char g_A23[(size_t)MSZ * KK];   // digits d2,d3 interleaved
__device__ __align__(16) signed char g_Bp[(size_t)NSZ * KK];    // w, 96w interleaved
__device__ double g_abs_sum;
__device__ float  g_inv_scale;

// ---------------- PTX helpers (non-'a' features only: valid for compute_103) ----------------
__device__ __forceinline__ uint32_t s2u(const void* p) {
    return (uint32_t)__cvta_generic_to_shared(p);
}
__device__ __forceinline__ uint32_t swz(uint32_t off) { return off ^ ((off >> 3) & 0x70); }

__device__ __forceinline__ void cp16(uint32_t dst, const void* src) {
    asm volatile("cp.async.cg.shared.global [%0], [%1], 16;" :: "r"(dst), "l"(src));
}
__device__ __forceinline__ void cp_commit() { asm volatile("cp.async.commit_group;" ::: "memory"); }
__device__ __forceinline__ void cp_wait2()  { asm volatile("cp.async.wait_group 2;" ::: "memory"); }

__device__ __forceinline__ void ldsm_x4(uint32_t& r0, uint32_t& r1, uint32_t& r2, uint32_t& r3,
                                        uint32_t addr) {
    asm volatile("ldmatrix.sync.aligned.m8n8.x4.shared.b16 {%0,%1,%2,%3}, [%4];"
                 : "=r"(r0), "=r"(r1), "=r"(r2), "=r"(r3) : "r"(addr));
}

// s8 m16n8k32: fragment byte layout identical to bf16 m16n8k16 (4B/reg at 4*tig, k-half +16B)
__device__ __forceinline__ void mma_s8(int* d, const uint32_t* a, const uint32_t* b) {
    asm volatile(
        "mma.sync.aligned.m16n8k32.row.col.s32.s8.s8.s32 "
        "{%0,%1,%2,%3}, {%4,%5,%6,%7}, {%8,%9}, {%0,%1,%2,%3};"
        : "+r"(d[0]), "+r"(d[1]), "+r"(d[2]), "+r"(d[3])
        : "r"(a[0]), "r"(a[1]), "r"(a[2]), "r"(a[3]), "r"(b[0]), "r"(b[1]));
}

// balanced base-96 digit: returns r in [-48,47], updates d := (d-r)/96 exactly
__device__ __forceinline__ int bdig(int& d) {
    int r = d % 96;
    if (r > 47) r -= 96;
    else if (r < -48) r += 96;
    d = (d - r) / 96;
    return r;
}

// ---------------- pre-pass: base-96 digit split of t = x*inS*wS ----------------
__global__ void split_kernel(const float4* __restrict__ x,
                             const float* __restrict__ inS,
                             const float* __restrict__ wS, int n4) {
    int i = blockIdx.x * blockDim.x + threadIdx.x;
    if (i >= n4) return;
    const float s = inS[0] * wS[0];
    const float q = fabsf(s) * QCONST;
    const float f = s * (1.0f / q);          // t*inv_q == x*f
    float4 v = x[i];
    float t[4] = {v.x, v.y, v.z, v.w};
    unsigned char b01[8], b23[8];
    #pragma unroll
    for (int j = 0; j < 4; j++) {
        int d = __float2int_rn(t[j] * f);
        d = max(min(d, DRANGE), -DRANGE);
        int d0 = bdig(d), d1 = bdig(d), d2 = bdig(d), d3 = bdig(d);
        b01[2 * j] = (unsigned char)(signed char)d0;
        b01[2 * j + 1] = (unsigned char)(signed char)d1;
        b23[2 * j] = (unsigned char)(signed char)d2;
        b23[2 * j + 1] = (unsigned char)(signed char)d3;
    }
    // flat element base e = 4*i; interleaved offset = 2*e = 8*i (8B aligned)
    *(unsigned long long*)&g_A01[(size_t)i * 8] = *(unsigned long long*)b01;
    *(unsigned long long*)&g_A23[(size_t)i * 8] = *(unsigned long long*)b23;
}

__global__ void wconv_kernel(const float4* __restrict__ w, int n4) {
    int i = blockIdx.x * blockDim.x + threadIdx.x;
    if (i >= n4) return;
    float4 v = w[i];
    float t[4] = {v.x, v.y, v.z, v.w};
    unsigned char b[8];
    #pragma unroll
    for (int j = 0; j < 4; j++) {
        int wi = (int)t[j];                          // exactly -1, 0, or 1
        b[2 * j] = (unsigned char)(signed char)wi;
        b[2 * j + 1] = (unsigned char)(signed char)(96 * wi);
    }
    *(unsigned long long*)&g_Bp[(size_t)i * 8] = *(unsigned long long*)b;
}

__global__ void reset_kernel() { g_abs_sum = 0.0; }

// ---------------- IMMA GEMM (exact int32 accumulation) ----------------
__global__ __launch_bounds__(THREADS, 1)
void gemm_kernel(float* __restrict__ C,
                 const float* __restrict__ inS, const float* __restrict__ wS) {
    extern __shared__ char smem[];
    const uint32_t sb = s2u(smem);

    const int tid = threadIdx.x, wid = tid >> 5, lane = tid & 31;
    const int wm = wid & 1;          // 2 warps in m -> 64 rows each
    const int wn = wid >> 1;         // 4 warps in n -> 32 cols each
    const int m0 = blockIdx.y * BM;
    const int n0 = blockIdx.x * BN;

    int acc01[4][4][4], acc23[4][4][4];
    #pragma unroll
    for (int i = 0; i < 4; i++)
        #pragma unroll
        for (int j = 0; j < 4; j++)
            #pragma unroll
            for (int r = 0; r < 4; r++) { acc01[i][j][r] = 0; acc23[i][j][r] = 0; }

    // --- cp.async stage loader: 3 planes x 128 rows x 128B, SW128 swizzled ---
    auto load_stage = [&](int kt) {
        const uint32_t stb = sb + (uint32_t)(kt % NSTAGE) * STAGE_BYTES;
        const int kb = kt * BKK;
        #pragma unroll
        for (int p = 0; p < 3; p++) {
            const signed char* base =
                (p == 0 ? g_A01 : p == 1 ? g_A23 : g_Bp) +
                (size_t)(p == 2 ? n0 : m0) * KK + kb;
            #pragma unroll
            for (int j = 0; j < 4; j++) {
                int e = tid + THREADS * j;          // 0..1023
                int row = e >> 3, c = e & 7;
                cp16(stb + p * PLANE_BYTES + swz(row * 128 + c * 16),
                     base + (size_t)row * KK + c * 16);
            }
        }
    };

    // --- per-lane ldmatrix components (byte-identical to proven bf16 mapping) ---
    const int a_row  = wm * 64 + (lane & 15);                       // + mt*16
    const int a_koff = (lane >> 4) * 16;                            // + ks*32
    const int b_row  = wn * 32 + ((lane >> 4) << 3) + (lane & 7);   // + pair*16
    const int b_koff = ((lane >> 3) & 1) * 16;                      // + ks*32

    load_stage(0); cp_commit();
    load_stage(1); cp_commit();

    for (int kt = 0; kt < KTILES; kt++) {
        if (kt + 2 < KTILES) load_stage(kt + 2);
        cp_commit();            // uniform group count (empty group in tail)
        cp_wait2();             // stage kt resident (this thread's groups)
        __syncthreads();        // publish all threads' loads

        const uint32_t stb = sb + (uint32_t)(kt % NSTAGE) * STAGE_BYTES;
        #pragma unroll
        for (int ks = 0; ks < 4; ks++) {
            // B' fragments for all 4 n-tiles (shared by both digit pairs)
            uint32_t bfr[2][4];
            #pragma unroll
            for (int pair = 0; pair < 2; pair++) {
                uint32_t off = (uint32_t)(b_row + pair * 16) * 128 + ks * 32 + b_koff;
                ldsm_x4(bfr[pair][0], bfr[pair][1], bfr[pair][2], bfr[pair][3],
                        stb + 2 * PLANE_BYTES + swz(off));
            }
            #pragma unroll
            for (int mt = 0; mt < 4; mt++) {
                uint32_t off = (uint32_t)(a_row + mt * 16) * 128 + ks * 32 + a_koff;
                uint32_t a0[4], a1[4];
                ldsm_x4(a0[0], a0[1], a0[2], a0[3], stb + swz(off));
                ldsm_x4(a1[0], a1[1], a1[2], a1[3], stb + PLANE_BYTES + swz(off));
                #pragma unroll
                for (int nt = 0; nt < 4; nt++) {
                    mma_s8(acc01[mt][nt], a0, &bfr[nt >> 1][(nt & 1) * 2]);
                    mma_s8(acc23[mt][nt], a1, &bfr[nt >> 1][(nt & 1) * 2]);
                }
            }
        }
        __syncthreads();        // protect buffer before reload
    }

    // ---------------- epilogue: out = q*(acc01 + 9216*acc23), store + abs-sum ----------------
    const float s = inS[0] * wS[0];
    const float q = fabsf(s) * QCONST;          // identical formula to split_kernel
    float asum = 0.f;
    {
        const int rbase = m0 + wm * 64 + (lane >> 2);
        const int cbase = n0 + wn * 32 + (lane & 3) * 2;
        #pragma unroll
        for (int mt = 0; mt < 4; mt++) {
            #pragma unroll
            for (int nt = 0; nt < 4; nt++) {
                float v[4];
                #pragma unroll
                for (int r = 0; r < 4; r++) {
                    // |acc| < 2^24 -> int->float exact; one fma + one mul rounding
                    float t0 = fmaf(9216.f, (float)acc23[mt][nt][r], (float)acc01[mt][nt][r]);
                    v[r] = q * t0;
                    asum += fabsf(v[r]);
                }
                float* p0 = C + (size_t)(rbase + mt * 16) * NSZ + cbase + nt * 8;
                float* p1 = p0 + 8 * NSZ;
                *(float2*)p0 = make_float2(v[0], v[1]);
                *(float2*)p1 = make_float2(v[2], v[3]);
            }
        }
    }

    __shared__ float red[THREADS / 32];
    #pragma unroll
    for (int off = 16; off > 0; off >>= 1)
        asum += __shfl_down_sync(0xffffffffu, asum, off);
    if (lane == 0) red[wid] = asum;
    __syncthreads();
    if (wid == 0) {
        float v = (lane < THREADS / 32) ? red[lane] : 0.f;
        #pragma unroll
        for (int off = 4; off > 0; off >>= 1)
            v += __shfl_down_sync(0xffffffffu, v, off);
        if (lane == 0) atomicAdd(&g_abs_sum, (double)v);
    }
}

// ---------------- finalize + quantize ----------------
__global__ void finalize_kernel(float* __restrict__ scale_slot, size_t mn) {
    double mean = g_abs_sum / (double)mn;
    float scale = (float)mean;
    if (scale < 1e-5f) scale = 1e-5f;
    *scale_slot = scale;
    g_inv_scale = (float)(1.0 / (double)scale);
}

__global__ void quantize_kernel(float4* __restrict__ C, int n4) {
    int i = blockIdx.x * blockDim.x + threadIdx.x;
    if (i >= n4) return;
    const float inv = g_inv_scale;
    float4 v = C[i];
    v.x = fminf(fmaxf(rintf(v.x * inv), -1.f), 1.f);
    v.y = fminf(fmaxf(rintf(v.y * inv), -1.f), 1.f);
    v.z = fminf(fmaxf(rintf(v.z * inv), -1.f), 1.f);
    v.w = fminf(fmaxf(rintf(v.w * inv), -1.f), 1.f);
    C[i] = v;
}

extern "C" void kernel_launch(void* const* d_in, const int* in_sizes, int n_in,
                              void* d_out, int out_size)
{
    const float* x   = (const float*)d_in[0];
    const float* inS = (const float*)d_in[1];
    const float* qw  = (const float*)d_in[2];
    const float* wS  = (const float*)d_in[3];
    float* out = (float*)d_out;
    const size_t mn = (size_t)MSZ * NSZ;

    cudaFuncSetAttribute(gemm_kernel, cudaFuncAttributeMaxDynamicSharedMemorySize, SMEM_BYTES);

    const int a4 = MSZ * KSZ / 4;
    split_kernel<<<(a4 + 255) / 256, 256>>>((const float4*)x, inS, wS, a4);
    const int w4 = NSZ * KSZ / 4;
    wconv_kernel<<<(w4 + 255) / 256, 256>>>((const float4*)qw, w4);
    reset_kernel<<<1, 1>>>();

    dim3 grid(NSZ / BN, MSZ / BM);   // (16, 128)
    gemm_kernel<<<grid, THREADS, SMEM_BYTES>>>(out, inS, wS);

    finalize_kernel<<<1, 1>>>(out + mn, mn);

    const int n4 = (int)(mn / 4);
    quantize_kernel<<<(n4 + 255) / 256, 256>>>((float4*)out, n4);
}

// round 10
// speedup vs baseline: 1.0013x; 1.0012x over previous
#include <cuda_runtime.h>
#include <cuda_bf16.h>
#include <cstdint>

#define MSZ 16384
#define NSZ 2048
#define KSZ 2048
#define KK (2 * KSZ)                      // virtual K (digit pairs interleaved)
#define BM 128
#define BN 128
#define BKK 128                           // virtual-k bytes per tile
#define KTILES (KK / BKK)                 // 32
#define THREADS 256
#define PLANE_BYTES (128 * 128)           // 16KB per plane per stage
#define STAGE_BYTES (3 * PLANE_BYTES)     // A01 + A23 + B' = 48KB
#define NSTAGE 3
#define SMEM_BYTES (NSTAGE * STAGE_BYTES) // 144KB

#define DRANGE 42000000                   // clamp for base-96 4-digit balanced rep
#define QCONST (8.0f / 42000000.0f)       // q = |inS*wS| * QCONST  (range = ±8 sigma)

// -------- scratch (device globals: the allowed scratch mechanism) --------
__device__ __align__(16) signed char g_A01[(size_t)MSZ * KK];   // digits d0,d1 interleaved
__device__ __align__(16) signed char g_A23[(size_t)MSZ * KK];   // digits d2,d3 interleaved
__device__ __align__(16) signed char g_Bp[(size_t)NSZ * KK];    // w, 96w interleaved
__device__ double g_abs_sum;
__device__ float  g_inv_scale;

// ---------------- PTX helpers (non-'a' features only: valid for compute_103) ----------------
__device__ __forceinline__ uint32_t s2u(const void* p) {
    return (uint32_t)__cvta_generic_to_shared(p);
}
__device__ __forceinline__ uint32_t swz(uint32_t off) { return off ^ ((off >> 3) & 0x70); }

__device__ __forceinline__ void cp16(uint32_t dst, const void* src) {
    asm volatile("cp.async.cg.shared.global [%0], [%1], 16;" :: "r"(dst), "l"(src));
}
__device__ __forceinline__ void cp_commit() { asm volatile("cp.async.commit_group;" ::: "memory"); }
__device__ __forceinline__ void cp_wait2()  { asm volatile("cp.async.wait_group 2;" ::: "memory"); }

__device__ __forceinline__ void ldsm_x4(uint32_t& r0, uint32_t& r1, uint32_t& r2, uint32_t& r3,
                                        uint32_t addr) {
    asm volatile("ldmatrix.sync.aligned.m8n8.x4.shared.b16 {%0,%1,%2,%3}, [%4];"
                 : "=r"(r0), "=r"(r1), "=r"(r2), "=r"(r3) : "r"(addr));
}

// s8 m16n8k32: fragment byte layout identical to bf16 m16n8k16 (4B/reg at 4*tig, k-half +16B)
__device__ __forceinline__ void mma_s8(int* d, const uint32_t* a, const uint32_t* b) {
    asm volatile(
        "mma.sync.aligned.m16n8k32.row.col.s32.s8.s8.s32 "
        "{%0,%1,%2,%3}, {%4,%5,%6,%7}, {%8,%9}, {%0,%1,%2,%3};"
        : "+r"(d[0]), "+r"(d[1]), "+r"(d[2]), "+r"(d[3])
        : "r"(a[0]), "r"(a[1]), "r"(a[2]), "r"(a[3]), "r"(b[0]), "r"(b[1]));
}

// balanced base-96 digit: returns r in [-48,47], updates d := (d-r)/96 exactly
__device__ __forceinline__ int bdig(int& d) {
    int r = d % 96;
    if (r > 47) r -= 96;
    else if (r < -48) r += 96;
    d = (d - r) / 96;
    return r;
}

// ---------------- pre-pass: base-96 digit split of t = x*inS*wS ----------------
__global__ void split_kernel(const float4* __restrict__ x,
                             const float* __restrict__ inS,
                             const float* __restrict__ wS, int n4) {
    int i = blockIdx.x * blockDim.x + threadIdx.x;
    if (i >= n4) return;
    const float s = inS[0] * wS[0];
    const float q = fabsf(s) * QCONST;
    const float f = s * (1.0f / q);          // t*inv_q == x*f
    float4 v = x[i];
    float t[4] = {v.x, v.y, v.z, v.w};
    unsigned char b01[8], b23[8];
    #pragma unroll
    for (int j = 0; j < 4; j++) {
        int d = __float2int_rn(t[j] * f);
        d = max(min(d, DRANGE), -DRANGE);
        int d0 = bdig(d), d1 = bdig(d), d2 = bdig(d), d3 = bdig(d);
        b01[2 * j] = (unsigned char)(signed char)d0;
        b01[2 * j + 1] = (unsigned char)(signed char)d1;
        b23[2 * j] = (unsigned char)(signed char)d2;
        b23[2 * j + 1] = (unsigned char)(signed char)d3;
    }
    // flat element base e = 4*i; interleaved offset = 2*e = 8*i (8B aligned)
    *(unsigned long long*)&g_A01[(size_t)i * 8] = *(unsigned long long*)b01;
    *(unsigned long long*)&g_A23[(size_t)i * 8] = *(unsigned long long*)b23;
}

__global__ void wconv_kernel(const float4* __restrict__ w, int n4) {
    int i = blockIdx.x * blockDim.x + threadIdx.x;
    if (i >= n4) return;
    float4 v = w[i];
    float t[4] = {v.x, v.y, v.z, v.w};
    unsigned char b[8];
    #pragma unroll
    for (int j = 0; j < 4; j++) {
        int wi = (int)t[j];                          // exactly -1, 0, or 1
        b[2 * j] = (unsigned char)(signed char)wi;
        b[2 * j + 1] = (unsigned char)(signed char)(96 * wi);
    }
    *(unsigned long long*)&g_Bp[(size_t)i * 8] = *(unsigned long long*)b;
}

__global__ void reset_kernel() { g_abs_sum = 0.0; }

// ---------------- IMMA GEMM (exact int32 accumulation) ----------------
__global__ __launch_bounds__(THREADS, 1)
void gemm_kernel(float* __restrict__ C,
                 const float* __restrict__ inS, const float* __restrict__ wS) {
    extern __shared__ char smem[];
    const uint32_t sb = s2u(smem);

    const int tid = threadIdx.x, wid = tid >> 5, lane = tid & 31;
    const int wm = wid & 1;          // 2 warps in m -> 64 rows each
    const int wn = wid >> 1;         // 4 warps in n -> 32 cols each
    const int m0 = blockIdx.y * BM;
    const int n0 = blockIdx.x * BN;

    int acc01[4][4][4], acc23[4][4][4];
    #pragma unroll
    for (int i = 0; i < 4; i++)
        #pragma unroll
        for (int j = 0; j < 4; j++)
            #pragma unroll
            for (int r = 0; r < 4; r++) { acc01[i][j][r] = 0; acc23[i][j][r] = 0; }

    // --- cp.async stage loader: 3 planes x 128 rows x 128B, SW128 swizzled ---
    auto load_stage = [&](int kt) {
        const uint32_t stb = sb + (uint32_t)(kt % NSTAGE) * STAGE_BYTES;
        const int kb = kt * BKK;
        #pragma unroll
        for (int p = 0; p < 3; p++) {
            const signed char* base =
                (p == 0 ? g_A01 : p == 1 ? g_A23 : g_Bp) +
                (size_t)(p == 2 ? n0 : m0) * KK + kb;
            #pragma unroll
            for (int j = 0; j < 4; j++) {
                int e = tid + THREADS * j;          // 0..1023
                int row = e >> 3, c = e & 7;
                cp16(stb + p * PLANE_BYTES + swz(row * 128 + c * 16),
                     base + (size_t)row * KK + c * 16);
            }
        }
    };

    // --- per-lane ldmatrix components (byte-identical to proven bf16 mapping) ---
    const int a_row  = wm * 64 + (lane & 15);                       // + mt*16
    const int a_koff = (lane >> 4) * 16;                            // + ks*32
    const int b_row  = wn * 32 + ((lane >> 4) << 3) + (lane & 7);   // + pair*16
    const int b_koff = ((lane >> 3) & 1) * 16;                      // + ks*32

    load_stage(0); cp_commit();
    load_stage(1); cp_commit();

    for (int kt = 0; kt < KTILES; kt++) {
        if (kt + 2 < KTILES) load_stage(kt + 2);
        cp_commit();            // uniform group count (empty group in tail)
        cp_wait2();             // stage kt resident (this thread's groups)
        __syncthreads();        // publish all threads' loads

        const uint32_t stb = sb + (uint32_t)(kt % NSTAGE) * STAGE_BYTES;
        #pragma unroll
        for (int ks = 0; ks < 4; ks++) {
            // B' fragments for all 4 n-tiles (shared by both digit pairs)
            uint32_t bfr[2][4];
            #pragma unroll
            for (int pair = 0; pair < 2; pair++) {
                uint32_t off = (uint32_t)(b_row + pair * 16) * 128 + ks * 32 + b_koff;
                ldsm_x4(bfr[pair][0], bfr[pair][1], bfr[pair][2], bfr[pair][3],
                        stb + 2 * PLANE_BYTES + swz(off));
            }
            #pragma unroll
            for (int mt = 0; mt < 4; mt++) {
                uint32_t off = (uint32_t)(a_row + mt * 16) * 128 + ks * 32 + a_koff;
                uint32_t a0[4], a1[4];
                ldsm_x4(a0[0], a0[1], a0[2], a0[3], stb + swz(off));
                ldsm_x4(a1[0], a1[1], a1[2], a1[3], stb + PLANE_BYTES + swz(off));
                #pragma unroll
                for (int nt = 0; nt < 4; nt++) {
                    mma_s8(acc01[mt][nt], a0, &bfr[nt >> 1][(nt & 1) * 2]);
                    mma_s8(acc23[mt][nt], a1, &bfr[nt >> 1][(nt & 1) * 2]);
                }
            }
        }
        __syncthreads();        // protect buffer before reload
    }

    // ---------------- epilogue: out = q*(acc01 + 9216*acc23), store + abs-sum ----------------
    const float s = inS[0] * wS[0];
    const float q = fabsf(s) * QCONST;          // identical formula to split_kernel
    float asum = 0.f;
    {
        const int rbase = m0 + wm * 64 + (lane >> 2);
        const int cbase = n0 + wn * 32 + (lane & 3) * 2;
        #pragma unroll
        for (int mt = 0; mt < 4; mt++) {
            #pragma unroll
            for (int nt = 0; nt < 4; nt++) {
                float v[4];
                #pragma unroll
                for (int r = 0; r < 4; r++) {
                    // |acc| < 2^24 -> int->float exact; one fma + one mul rounding
                    float t0 = fmaf(9216.f, (float)acc23[mt][nt][r], (float)acc01[mt][nt][r]);
                    v[r] = q * t0;
                    asum += fabsf(v[r]);
                }
                float* p0 = C + (size_t)(rbase + mt * 16) * NSZ + cbase + nt * 8;
                float* p1 = p0 + 8 * NSZ;
                *(float2*)p0 = make_float2(v[0], v[1]);
                *(float2*)p1 = make_float2(v[2], v[3]);
            }
        }
    }

    __shared__ float red[THREADS / 32];
    #pragma unroll
    for (int off = 16; off > 0; off >>= 1)
        asum += __shfl_down_sync(0xffffffffu, asum, off);
    if (lane == 0) red[wid] = asum;
    __syncthreads();
    if (wid == 0) {
        float v = (lane < THREADS / 32) ? red[lane] : 0.f;
        #pragma unroll
        for (int off = 4; off > 0; off >>= 1)
            v += __shfl_down_sync(0xffffffffu, v, off);
        if (lane == 0) atomicAdd(&g_abs_sum, (double)v);
    }
}

// ---------------- finalize + quantize ----------------
__global__ void finalize_kernel(float* __restrict__ scale_slot, size_t mn) {
    double mean = g_abs_sum / (double)mn;
    float scale = (float)mean;
    if (scale < 1e-5f) scale = 1e-5f;
    *scale_slot = scale;
    g_inv_scale = (float)(1.0 / (double)scale);
}

__global__ void quantize_kernel(float4* __restrict__ C, int n4) {
    int i = blockIdx.x * blockDim.x + threadIdx.x;
    if (i >= n4) return;
    const float inv = g_inv_scale;
    float4 v = C[i];
    v.x = fminf(fmaxf(rintf(v.x * inv), -1.f), 1.f);
    v.y = fminf(fmaxf(rintf(v.y * inv), -1.f), 1.f);
    v.z = fminf(fmaxf(rintf(v.z * inv), -1.f), 1.f);
    v.w = fminf(fmaxf(rintf(v.w * inv), -1.f), 1.f);
    C[i] = v;
}

extern "C" void kernel_launch(void* const* d_in, const int* in_sizes, int n_in,
                              void* d_out, int out_size)
{
    const float* x   = (const float*)d_in[0];
    const float* inS = (const float*)d_in[1];
    const float* qw  = (const float*)d_in[2];
    const float* wS  = (const float*)d_in[3];
    float* out = (float*)d_out;
    const size_t mn = (size_t)MSZ * NSZ;

    cudaFuncSetAttribute(gemm_kernel, cudaFuncAttributeMaxDynamicSharedMemorySize, SMEM_BYTES);

    const int a4 = MSZ * KSZ / 4;
    split_kernel<<<(a4 + 255) / 256, 256>>>((const float4*)x, inS, wS, a4);
    const int w4 = NSZ * KSZ / 4;
    wconv_kernel<<<(w4 + 255) / 256, 256>>>((const float4*)qw, w4);
    reset_kernel<<<1, 1>>>();

    dim3 grid(NSZ / BN, MSZ / BM);   // (16, 128)
    gemm_kernel<<<grid, THREADS, SMEM_BYTES>>>(out, inS, wS);

    finalize_kernel<<<1, 1>>>(out + mn, mn);

    const int n4 = (int)(mn / 4);
    quantize_kernel<<<(n4 + 255) / 256, 256>>>((float4*)out, n4);
}